// round 9
// baseline (speedup 1.0000x reference)
#include <cuda_runtime.h>
#include <cuda_fp16.h>
#include <stdint.h>
#include <math.h>

#define DI __device__ __forceinline__

#define BB 1024
#define HH 2048
#define EE 1024
#define K1 3072
#define N1 8192
#define K2 2048

// ---- device scratch ----
__device__ __align__(256) __half g_A1[BB * K1];
__device__ __align__(256) __half g_W1[(size_t)N1 * K1];   // gate-interleaved rows: n' = 4*j + gate
__device__ __align__(256) __half g_W2[EE * K2];
__device__ __align__(256) __half g_A2[BB * K2];
__device__ __align__(256) float g_Part[4 * BB * EE];      // split-K partials for GEMM2

// ---- helpers ----
DI uint32_t smem_u32(const void* p) {
    uint32_t a;
    asm("{ .reg .u64 t; cvta.to.shared.u64 t, %1; cvt.u32.u64 %0, t; }" : "=r"(a) : "l"(p));
    return a;
}
DI float sigm(float v) { return 1.0f / (1.0f + expf(-v)); }

DI void ldsm4(uint32_t* r, uint32_t addr) {
    asm volatile("ldmatrix.sync.aligned.m8n8.x4.shared.b16 {%0,%1,%2,%3}, [%4];"
                 : "=r"(r[0]), "=r"(r[1]), "=r"(r[2]), "=r"(r[3]) : "r"(addr));
}
DI void mma_f16(float* c, const uint32_t* a, const uint32_t* b) {
    asm volatile(
        "mma.sync.aligned.m16n8k16.row.col.f32.f16.f16.f32 "
        "{%0,%1,%2,%3}, {%4,%5,%6,%7}, {%8,%9}, {%0,%1,%2,%3};"
        : "+f"(c[0]), "+f"(c[1]), "+f"(c[2]), "+f"(c[3])
        : "r"(a[0]), "r"(a[1]), "r"(a[2]), "r"(a[3]), "r"(b[0]), "r"(b[1]));
}

// copy R rows x 128B (64 fp16) into smem rows padded to 144B
template <int R, int KDIM>
DI void cp_rows64(uint32_t sdst, const __half* g, int tid) {
#pragma unroll
    for (int it = 0; it < R * 8; it += 256) {
        int i = it + tid;
        int row = i >> 3, ch = i & 7;
        asm volatile("cp.async.cg.shared.global [%0], [%1], 16;"
                     :: "r"(sdst + row * 144 + ch * 16),
                        "l"((const char*)(g + (size_t)row * KDIM) + ch * 16));
    }
}
template <int BN, int KDIM>
DI void stage_cp(uint32_t sb, const __half* gA, const __half* gW, int k0, int tid) {
    cp_rows64<128, KDIM>(sb, gA + k0, tid);
    cp_rows64<BN, KDIM>(sb + 128 * 144, gW + k0, tid);
}

DI uint4 pack8(float4 a, float4 b) {
    __half2 h0 = __float22half2_rn(make_float2(a.x, a.y));
    __half2 h1 = __float22half2_rn(make_float2(a.z, a.w));
    __half2 h2 = __float22half2_rn(make_float2(b.x, b.y));
    __half2 h3 = __float22half2_rn(make_float2(b.z, b.w));
    uint4 r;
    r.x = *(uint32_t*)&h0; r.y = *(uint32_t*)&h1;
    r.z = *(uint32_t*)&h2; r.w = *(uint32_t*)&h3;
    return r;
}

// ---- merged convert kernel: fp32 -> fp16, 8 elems/thread ----
#define NC_A1 (BB * K1 / 8)
#define NC_W1 ((int)((size_t)N1 * K1 / 8))
#define NC_W2 (EE * K2 / 8)
__global__ void k_conv(const float* __restrict__ x, const float* __restrict__ h,
                       const float* __restrict__ wxi, const float* __restrict__ whi_,
                       const float* __restrict__ wxg, const float* __restrict__ whg,
                       const float* __restrict__ wxf, const float* __restrict__ whf,
                       const float* __restrict__ wxo, const float* __restrict__ who_,
                       const float* __restrict__ why) {
    int idx = blockIdx.x * 256 + threadIdx.x;
    if (idx < NC_A1) {
        int i8 = idx * 8;
        int b = i8 / K1, k = i8 - b * K1;
        const float* src = (k < EE) ? &x[(size_t)b * EE + k] : &h[(size_t)b * HH + (k - EE)];
        *(uint4*)&g_A1[i8] = pack8(*(const float4*)src, *(const float4*)(src + 4));
    } else if (idx < NC_A1 + NC_W1) {
        size_t i8 = (size_t)(idx - NC_A1) * 8;
        int n = (int)(i8 / K1);                  // interleaved row: n' = 4*j + gate
        int k = (int)(i8 - (size_t)n * K1);
        int j = n >> 2, g = n & 3;
        const float* src;
        if (k < EE) {
            const float* a = (g == 0) ? wxi : (g == 1) ? wxg : (g == 2) ? wxf : wxo;
            src = &a[(size_t)j * EE + k];
        } else {
            const float* a = (g == 0) ? whi_ : (g == 1) ? whg : (g == 2) ? whf : who_;
            src = &a[(size_t)j * HH + (k - EE)];
        }
        *(uint4*)&g_W1[i8] = pack8(*(const float4*)src, *(const float4*)(src + 4));
    } else if (idx < NC_A1 + NC_W1 + NC_W2) {
        int i8 = (idx - NC_A1 - NC_W1) * 8;
        *(uint4*)&g_W2[i8] = pack8(*(const float4*)&why[i8], *(const float4*)&why[i8 + 4]);
    }
}

// ---- fp16 HMMA GEMM, BK=64, 2-stage ring, 3 CTAs/SM ----
// MODE 0: CTA 128x128, warp 64x32, gate-interleaved preact + fused gates epilogue
// MODE 1: CTA 128x64, warp 32x32, split-K partial -> g_Part[z][b][n]
template <int BN, int WM, int WN, int S, int KDIM, int MODE>
__global__ void __launch_bounds__(256, 3)
k_gemm(const float* __restrict__ cin,
       const float* __restrict__ Bi, const float* __restrict__ Bg,
       const float* __restrict__ Bf, const float* __restrict__ Bo,
       float* __restrict__ outp) {
    constexpr int NWM = 128 / WM;
    constexpr int MI = WM / 16, NI = WN / 8;
    constexpr int STAGE = (128 + BN) * 144;

    extern __shared__ char smem[];
    uint32_t sbase = smem_u32(smem);
    const int tid = threadIdx.x, lane = tid & 31, wid = tid >> 5;
    const int wm = (wid % NWM) * WM, wn = (wid / NWM) * WN;
    const int nt = blockIdx.x, mt = blockIdx.y;
    const int kOff = MODE ? blockIdx.z * (S * 64) : 0;

    const __half* gA = (MODE == 0 ? g_A1 : g_A2) + (size_t)mt * 128 * KDIM + kOff;
    const __half* gW = (MODE == 0 ? g_W1 : g_W2) + (size_t)nt * BN * KDIM + kOff;

    float acc[MI][NI][4];
#pragma unroll
    for (int mi = 0; mi < MI; mi++)
#pragma unroll
        for (int ni = 0; ni < NI; ni++)
#pragma unroll
            for (int q = 0; q < 4; q++) acc[mi][ni][q] = 0.0f;

    stage_cp<BN, KDIM>(sbase, gA, gW, 0, tid);
    asm volatile("cp.async.commit_group;" ::: "memory");

    const uint32_t bRowOff = ((uint32_t)(((lane >> 4) << 3) + (lane & 7))) * 144
                           + ((lane >> 3) & 1) * 16;
    const uint32_t aRowOff = ((uint32_t)(lane & 15)) * 144 + (lane >> 4) * 16;

    for (int s = 0; s < S; ++s) {
        // stage s data ready; also guarantees every warp finished compute(s-1)
        asm volatile("cp.async.wait_group 0;" ::: "memory");
        __syncthreads();
        if (s + 1 < S) {   // overwrites buf (s+1)&1 (compute(s-1)'s buffer) — safe after sync
            stage_cp<BN, KDIM>(sbase + ((s + 1) & 1) * STAGE, gA, gW, (s + 1) * 64, tid);
            asm volatile("cp.async.commit_group;" ::: "memory");
        }

        uint32_t sb = sbase + (uint32_t)(s & 1) * STAGE;
        uint32_t sA = sb + (uint32_t)wm * 144 + aRowOff;
        uint32_t sW = sb + 128 * 144 + (uint32_t)wn * 144 + bRowOff;

#pragma unroll
        for (int kk = 0; kk < 4; kk++) {
            uint32_t Bb[NI][2];
#pragma unroll
            for (int nj = 0; nj < NI; nj += 2) {
                uint32_t r[4];
                ldsm4(r, sW + nj * 8 * 144 + kk * 32);
                Bb[nj][0] = r[0]; Bb[nj][1] = r[1];
                Bb[nj + 1][0] = r[2]; Bb[nj + 1][1] = r[3];
            }
#pragma unroll
            for (int mi = 0; mi < MI; mi++) {
                uint32_t Ab[4];
                ldsm4(Ab, sA + mi * 16 * 144 + kk * 32);
#pragma unroll
                for (int ni = 0; ni < NI; ni++)
                    mma_f16(acc[mi][ni], Ab, Bb[ni]);
            }
        }
    }

    if (MODE == 1) {
        float* dst = g_Part + (size_t)blockIdx.z * BB * EE;
#pragma unroll
        for (int mi = 0; mi < MI; mi++)
#pragma unroll
            for (int ni = 0; ni < NI; ni++) {
                int m = mt * 128 + wm + mi * 16 + (lane >> 2);
                int n = nt * BN + wn + ni * 8 + (lane & 3) * 2;
                *(float2*)&dst[(size_t)m * EE + n] = make_float2(acc[mi][ni][0], acc[mi][ni][1]);
                *(float2*)&dst[(size_t)(m + 8) * EE + n] = make_float2(acc[mi][ni][2], acc[mi][ni][3]);
            }
    } else {
        // fused gates epilogue. sF (128x132 floats = 67.6 KB) overlaps the stage
        // buffers -> must sync so no warp still reads the last stage.
        float* sF = (float*)smem;
        __syncthreads();
#pragma unroll
        for (int mi = 0; mi < MI; mi++)
#pragma unroll
            for (int ni = 0; ni < NI; ni++) {
                int ml = wm + mi * 16 + (lane >> 2);
                int nl = wn + ni * 8 + (lane & 3) * 2;
                *(float2*)&sF[ml * 132 + nl] = make_float2(acc[mi][ni][0], acc[mi][ni][1]);
                *(float2*)&sF[(ml + 8) * 132 + nl] = make_float2(acc[mi][ni][2], acc[mi][ni][3]);
            }
        __syncthreads();
        const int j = nt * 32 + lane;
        const float bi = Bi[j], bg = Bg[j], bf = Bf[j], bo = Bo[j];
#pragma unroll 4
        for (int it = 0; it < 16; it++) {
            int ml = it * 8 + wid;
            float4 v = *(const float4*)&sF[ml * 132 + lane * 4];  // i,g,f,o preacts
            int b = mt * 128 + ml;
            float i = sigm(v.x + bi);
            float g = tanhf(v.y + bg);
            float f = sigm(v.z + bf);
            float o = sigm(v.w + bo);
            float cn = f * cin[(size_t)b * HH + j] + i * g;
            float hn = o * cn;
            outp[BB * EE + (size_t)b * HH + j] = cn;
            outp[BB * EE + BB * HH + (size_t)b * HH + j] = hn;
            g_A2[(size_t)b * HH + j] = __float2half(hn);
        }
    }
}

// ---- final y: reduce 4 split-K partials + bias + tanh ----
__global__ void k_y(const float* __restrict__ By, float* __restrict__ out) {
    int idx = blockIdx.x * 256 + threadIdx.x;
    if (idx >= BB * EE / 4) return;
    int base = idx * 4;
    int n = base & (EE - 1);
    float4 s0 = *(const float4*)&g_Part[base];
    float4 s1 = *(const float4*)&g_Part[BB * EE + base];
    float4 s2 = *(const float4*)&g_Part[2 * BB * EE + base];
    float4 s3 = *(const float4*)&g_Part[3 * BB * EE + base];
    float4 bv = *(const float4*)&By[n];
    float4 r;
    r.x = tanhf(s0.x + s1.x + s2.x + s3.x + bv.x);
    r.y = tanhf(s0.y + s1.y + s2.y + s3.y + bv.y);
    r.z = tanhf(s0.z + s1.z + s2.z + s3.z + bv.z);
    r.w = tanhf(s0.w + s1.w + s2.w + s3.w + bv.w);
    *(float4*)&out[base] = r;
}

extern "C" void kernel_launch(void* const* d_in, const int* in_sizes, int n_in,
                              void* d_out, int out_size) {
    const float* x   = (const float*)d_in[0];
    const float* c   = (const float*)d_in[1];
    const float* h   = (const float*)d_in[2];
    const float* wxi = (const float*)d_in[3];
    const float* whi = (const float*)d_in[4];
    const float* Bi  = (const float*)d_in[5];
    const float* wxg = (const float*)d_in[6];
    const float* whg = (const float*)d_in[7];
    const float* Bg  = (const float*)d_in[8];
    const float* wxf = (const float*)d_in[9];
    const float* whf = (const float*)d_in[10];
    const float* Bf  = (const float*)d_in[11];
    const float* wxo = (const float*)d_in[12];
    const float* who = (const float*)d_in[13];
    const float* Bo  = (const float*)d_in[14];
    const float* why = (const float*)d_in[15];
    const float* By  = (const float*)d_in[16];
    float* out = (float*)d_out;

    const int SMEM1 = 2 * (128 + 128) * 144;   // 73728
    const int SMEM2 = 2 * (128 + 64) * 144;    // 55296
    cudaFuncSetAttribute(k_gemm<128, 64, 32, 48, K1, 0>,
                         cudaFuncAttributeMaxDynamicSharedMemorySize, SMEM1);
    cudaFuncSetAttribute(k_gemm<64, 32, 32, 8, K2, 1>,
                         cudaFuncAttributeMaxDynamicSharedMemorySize, SMEM2);

    const int NCHUNK = NC_A1 + NC_W1 + NC_W2;
    k_conv<<<(NCHUNK + 255) / 256, 256>>>(x, h, wxi, whi, wxg, whg, wxf, whf, wxo, who, why);
    k_gemm<128, 64, 32, 48, K1, 0><<<dim3(N1 / 128, BB / 128), 256, SMEM1>>>(
        c, Bi, Bg, Bf, Bo, out);
    k_gemm<64, 32, 32, 8, K2, 1><<<dim3(EE / 64, BB / 128, 4), 256, SMEM2>>>(
        nullptr, nullptr, nullptr, nullptr, nullptr, nullptr);
    k_y<<<(BB * EE / 4) / 256, 256>>>(By, out);
}

// round 11
// speedup vs baseline: 1.2392x; 1.2392x over previous
#include <cuda_runtime.h>
#include <cuda_fp16.h>
#include <stdint.h>
#include <math.h>

#define DI __device__ __forceinline__

#define BB 1024
#define HH 2048
#define EE 1024
#define K1 3072
#define N1 8192
#define K2 2048

// ---- device scratch ----
__device__ __align__(256) __half g_A1[BB * K1];
__device__ __align__(256) __half g_W1[(size_t)N1 * K1];   // gate-interleaved rows: n' = 4*j + gate
__device__ __align__(256) __half g_W2[EE * K2];
__device__ __align__(256) __half g_A2[BB * K2];
__device__ __align__(256) float g_Part[4 * BB * EE];      // split-K partials for GEMM2

// ---- helpers ----
DI uint32_t smem_u32(const void* p) {
    uint32_t a;
    asm("{ .reg .u64 t; cvta.to.shared.u64 t, %1; cvt.u32.u64 %0, t; }" : "=r"(a) : "l"(p));
    return a;
}
DI float sigm(float v) { return 1.0f / (1.0f + expf(-v)); }

DI void ldsm4(uint32_t* r, uint32_t addr) {
    asm volatile("ldmatrix.sync.aligned.m8n8.x4.shared.b16 {%0,%1,%2,%3}, [%4];"
                 : "=r"(r[0]), "=r"(r[1]), "=r"(r[2]), "=r"(r[3]) : "r"(addr));
}
DI void mma_f16(float* c, const uint32_t* a, const uint32_t* b) {
    asm volatile(
        "mma.sync.aligned.m16n8k16.row.col.f32.f16.f16.f32 "
        "{%0,%1,%2,%3}, {%4,%5,%6,%7}, {%8,%9}, {%0,%1,%2,%3};"
        : "+f"(c[0]), "+f"(c[1]), "+f"(c[2]), "+f"(c[3])
        : "r"(a[0]), "r"(a[1]), "r"(a[2]), "r"(a[3]), "r"(b[0]), "r"(b[1]));
}

// copy R rows x 128B (64 fp16) into smem rows padded to 144B
template <int R, int KDIM>
DI void cp_rows64(uint32_t sdst, const __half* g, int tid) {
#pragma unroll
    for (int it = 0; it < R * 8; it += 256) {
        int i = it + tid;
        int row = i >> 3, ch = i & 7;
        asm volatile("cp.async.cg.shared.global [%0], [%1], 16;"
                     :: "r"(sdst + row * 144 + ch * 16),
                        "l"((const char*)(g + (size_t)row * KDIM) + ch * 16));
    }
}
template <int BN, int KDIM>
DI void stage_cp(uint32_t sb, const __half* gA, const __half* gW, int k0, int tid) {
    cp_rows64<128, KDIM>(sb, gA + k0, tid);
    cp_rows64<BN, KDIM>(sb + 128 * 144, gW + k0, tid);
}

DI uint4 pack8(float4 a, float4 b) {
    __half2 h0 = __float22half2_rn(make_float2(a.x, a.y));
    __half2 h1 = __float22half2_rn(make_float2(a.z, a.w));
    __half2 h2 = __float22half2_rn(make_float2(b.x, b.y));
    __half2 h3 = __float22half2_rn(make_float2(b.z, b.w));
    uint4 r;
    r.x = *(uint32_t*)&h0; r.y = *(uint32_t*)&h1;
    r.z = *(uint32_t*)&h2; r.w = *(uint32_t*)&h3;
    return r;
}

// ---- merged convert kernel: fp32 -> fp16, 8 elems/thread ----
#define NC_A1 (BB * K1 / 8)
#define NC_W1 ((int)((size_t)N1 * K1 / 8))
#define NC_W2 (EE * K2 / 8)
__global__ void k_conv(const float* __restrict__ x, const float* __restrict__ h,
                       const float* __restrict__ wxi, const float* __restrict__ whi_,
                       const float* __restrict__ wxg, const float* __restrict__ whg,
                       const float* __restrict__ wxf, const float* __restrict__ whf,
                       const float* __restrict__ wxo, const float* __restrict__ who_,
                       const float* __restrict__ why) {
    int idx = blockIdx.x * 256 + threadIdx.x;
    if (idx < NC_A1) {
        int i8 = idx * 8;
        int b = i8 / K1, k = i8 - b * K1;
        const float* src = (k < EE) ? &x[(size_t)b * EE + k] : &h[(size_t)b * HH + (k - EE)];
        *(uint4*)&g_A1[i8] = pack8(*(const float4*)src, *(const float4*)(src + 4));
    } else if (idx < NC_A1 + NC_W1) {
        size_t i8 = (size_t)(idx - NC_A1) * 8;
        int n = (int)(i8 / K1);                  // interleaved row: n' = 4*j + gate
        int k = (int)(i8 - (size_t)n * K1);
        int j = n >> 2, g = n & 3;
        const float* src;
        if (k < EE) {
            const float* a = (g == 0) ? wxi : (g == 1) ? wxg : (g == 2) ? wxf : wxo;
            src = &a[(size_t)j * EE + k];
        } else {
            const float* a = (g == 0) ? whi_ : (g == 1) ? whg : (g == 2) ? whf : who_;
            src = &a[(size_t)j * HH + (k - EE)];
        }
        *(uint4*)&g_W1[i8] = pack8(*(const float4*)src, *(const float4*)(src + 4));
    } else if (idx < NC_A1 + NC_W1 + NC_W2) {
        int i8 = (idx - NC_A1 - NC_W1) * 8;
        *(uint4*)&g_W2[i8] = pack8(*(const float4*)&why[i8], *(const float4*)&why[i8 + 4]);
    }
}

// ---- fp16 HMMA GEMM: CTA 128x64, warp 32x32, BK=64, 2-stage, 3 CTAs/SM ----
// MODE 0: gate-interleaved preact + fused gates epilogue -> out(c,h), g_A2
// MODE 1: split-K partial -> g_Part[z][b][n]
template <int S, int KDIM, int MODE>
__global__ void __launch_bounds__(256, 3)
k_gemm(const float* __restrict__ cin,
       const float* __restrict__ Bi, const float* __restrict__ Bg,
       const float* __restrict__ Bf, const float* __restrict__ Bo,
       float* __restrict__ outp) {
    constexpr int BN = 64;
    constexpr int MI = 2, NI = 4;                 // warp tile 32x32
    constexpr int STAGE = (128 + BN) * 144;

    extern __shared__ char smem[];
    uint32_t sbase = smem_u32(smem);
    const int tid = threadIdx.x, lane = tid & 31, wid = tid >> 5;
    const int wm = (wid & 3) * 32, wn = (wid >> 2) * 32;   // 4 x 2 warps
    const int nt = blockIdx.x, mt = blockIdx.y;
    const int kOff = MODE ? blockIdx.z * (S * 64) : 0;

    const __half* gA = (MODE == 0 ? g_A1 : g_A2) + (size_t)mt * 128 * KDIM + kOff;
    const __half* gW = (MODE == 0 ? g_W1 : g_W2) + (size_t)nt * BN * KDIM + kOff;

    float acc[MI][NI][4];
#pragma unroll
    for (int mi = 0; mi < MI; mi++)
#pragma unroll
        for (int ni = 0; ni < NI; ni++)
#pragma unroll
            for (int q = 0; q < 4; q++) acc[mi][ni][q] = 0.0f;

    stage_cp<BN, KDIM>(sbase, gA, gW, 0, tid);
    asm volatile("cp.async.commit_group;" ::: "memory");

    const uint32_t bRowOff = ((uint32_t)(((lane >> 4) << 3) + (lane & 7))) * 144
                           + ((lane >> 3) & 1) * 16;
    const uint32_t aRowOff = ((uint32_t)(lane & 15)) * 144 + (lane >> 4) * 16;

    for (int s = 0; s < S; ++s) {
        asm volatile("cp.async.wait_group 0;" ::: "memory");
        __syncthreads();
        if (s + 1 < S) {   // overwrites compute(s-1)'s buffer — safe after the sync
            stage_cp<BN, KDIM>(sbase + ((s + 1) & 1) * STAGE, gA, gW, (s + 1) * 64, tid);
            asm volatile("cp.async.commit_group;" ::: "memory");
        }

        uint32_t sb = sbase + (uint32_t)(s & 1) * STAGE;
        uint32_t sA = sb + (uint32_t)wm * 144 + aRowOff;
        uint32_t sW = sb + 128 * 144 + (uint32_t)wn * 144 + bRowOff;

#pragma unroll
        for (int kk = 0; kk < 4; kk++) {
            uint32_t Bb[NI][2];
#pragma unroll
            for (int nj = 0; nj < NI; nj += 2) {
                uint32_t r[4];
                ldsm4(r, sW + nj * 8 * 144 + kk * 32);
                Bb[nj][0] = r[0]; Bb[nj][1] = r[1];
                Bb[nj + 1][0] = r[2]; Bb[nj + 1][1] = r[3];
            }
#pragma unroll
            for (int mi = 0; mi < MI; mi++) {
                uint32_t Ab[4];
                ldsm4(Ab, sA + mi * 16 * 144 + kk * 32);
#pragma unroll
                for (int ni = 0; ni < NI; ni++)
                    mma_f16(acc[mi][ni], Ab, Bb[ni]);
            }
        }
    }

    if (MODE == 1) {
        float* dst = g_Part + (size_t)blockIdx.z * BB * EE;
#pragma unroll
        for (int mi = 0; mi < MI; mi++)
#pragma unroll
            for (int ni = 0; ni < NI; ni++) {
                int m = mt * 128 + wm + mi * 16 + (lane >> 2);
                int n = nt * BN + wn + ni * 8 + (lane & 3) * 2;
                *(float2*)&dst[(size_t)m * EE + n] = make_float2(acc[mi][ni][0], acc[mi][ni][1]);
                *(float2*)&dst[(size_t)(m + 8) * EE + n] = make_float2(acc[mi][ni][2], acc[mi][ni][3]);
            }
    } else {
        // fused gates epilogue. sF = 128 x 68 floats (34.8 KB) overlaps stage buffers.
        float* sF = (float*)smem;
        __syncthreads();
#pragma unroll
        for (int mi = 0; mi < MI; mi++)
#pragma unroll
            for (int ni = 0; ni < NI; ni++) {
                int ml = wm + mi * 16 + (lane >> 2);
                int nl = wn + ni * 8 + (lane & 3) * 2;
                *(float2*)&sF[ml * 68 + nl] = make_float2(acc[mi][ni][0], acc[mi][ni][1]);
                *(float2*)&sF[(ml + 8) * 68 + nl] = make_float2(acc[mi][ni][2], acc[mi][ni][3]);
            }
        __syncthreads();
        const int jj = lane & 15;              // local j within the 16 this CTA owns
        const int j = nt * 16 + jj;
        const float bi = Bi[j], bg = Bg[j], bf = Bf[j], bo = Bo[j];
#pragma unroll 4
        for (int it = 0; it < 8; it++) {
            int ml = it * 16 + wid * 2 + (lane >> 4);
            float4 v = *(const float4*)&sF[ml * 68 + jj * 4];  // i,g,f,o preacts
            int b = mt * 128 + ml;
            float i = sigm(v.x + bi);
            float g = tanhf(v.y + bg);
            float f = sigm(v.z + bf);
            float o = sigm(v.w + bo);
            float cn = f * cin[(size_t)b * HH + j] + i * g;
            float hn = o * cn;
            outp[BB * EE + (size_t)b * HH + j] = cn;
            outp[BB * EE + BB * HH + (size_t)b * HH + j] = hn;
            g_A2[(size_t)b * HH + j] = __float2half(hn);
        }
    }
}

// ---- final y: reduce 4 split-K partials + bias + tanh ----
__global__ void k_y(const float* __restrict__ By, float* __restrict__ out) {
    int idx = blockIdx.x * 256 + threadIdx.x;
    if (idx >= BB * EE / 4) return;
    int base = idx * 4;
    int n = base & (EE - 1);
    float4 s0 = *(const float4*)&g_Part[base];
    float4 s1 = *(const float4*)&g_Part[BB * EE + base];
    float4 s2 = *(const float4*)&g_Part[2 * BB * EE + base];
    float4 s3 = *(const float4*)&g_Part[3 * BB * EE + base];
    float4 bv = *(const float4*)&By[n];
    float4 r;
    r.x = tanhf(s0.x + s1.x + s2.x + s3.x + bv.x);
    r.y = tanhf(s0.y + s1.y + s2.y + s3.y + bv.y);
    r.z = tanhf(s0.z + s1.z + s2.z + s3.z + bv.z);
    r.w = tanhf(s0.w + s1.w + s2.w + s3.w + bv.w);
    *(float4*)&out[base] = r;
}

extern "C" void kernel_launch(void* const* d_in, const int* in_sizes, int n_in,
                              void* d_out, int out_size) {
    const float* x   = (const float*)d_in[0];
    const float* c   = (const float*)d_in[1];
    const float* h   = (const float*)d_in[2];
    const float* wxi = (const float*)d_in[3];
    const float* whi = (const float*)d_in[4];
    const float* Bi  = (const float*)d_in[5];
    const float* wxg = (const float*)d_in[6];
    const float* whg = (const float*)d_in[7];
    const float* Bg  = (const float*)d_in[8];
    const float* wxf = (const float*)d_in[9];
    const float* whf = (const float*)d_in[10];
    const float* Bf  = (const float*)d_in[11];
    const float* wxo = (const float*)d_in[12];
    const float* who = (const float*)d_in[13];
    const float* Bo  = (const float*)d_in[14];
    const float* why = (const float*)d_in[15];
    const float* By  = (const float*)d_in[16];
    float* out = (float*)d_out;

    const int SMEM = 2 * (128 + 64) * 144;   // 55296
    cudaFuncSetAttribute(k_gemm<48, K1, 0>, cudaFuncAttributeMaxDynamicSharedMemorySize, SMEM);
    cudaFuncSetAttribute(k_gemm<8, K2, 1>, cudaFuncAttributeMaxDynamicSharedMemorySize, SMEM);

    const int NCHUNK = NC_A1 + NC_W1 + NC_W2;
    k_conv<<<(NCHUNK + 255) / 256, 256>>>(x, h, wxi, whi, wxg, whg, wxf, whf, wxo, who, why);
    k_gemm<48, K1, 0><<<dim3(N1 / 64, BB / 128), 256, SMEM>>>(c, Bi, Bg, Bf, Bo, out);
    k_gemm<8, K2, 1><<<dim3(EE / 64, BB / 128, 4), 256, SMEM>>>(
        nullptr, nullptr, nullptr, nullptr, nullptr, nullptr);
    k_y<<<(BB * EE / 4) / 256, 256>>>(By, out);
}

// round 12
// speedup vs baseline: 1.7540x; 1.4154x over previous
#include <cuda_runtime.h>
#include <cuda_fp16.h>
#include <stdint.h>
#include <math.h>

#define DI __device__ __forceinline__

#define BB 1024
#define HH 2048
#define EE 1024
#define K1 3072
#define N1 8192
#define K2 2048

// ---- device scratch ----
__device__ __align__(256) __half g_A1[BB * K1];
__device__ __align__(256) __half g_W1[(size_t)N1 * K1];   // gate-interleaved rows: n' = 4*j + gate
__device__ __align__(256) __half g_W2[EE * K2];
__device__ __align__(256) __half g_A2[BB * K2];
__device__ __align__(256) float g_Part[4 * BB * EE];      // split-K partials for GEMM2

// ---- helpers ----
DI uint32_t smem_u32(const void* p) {
    uint32_t a;
    asm("{ .reg .u64 t; cvta.to.shared.u64 t, %1; cvt.u32.u64 %0, t; }" : "=r"(a) : "l"(p));
    return a;
}
DI float sigm(float v) { return 1.0f / (1.0f + expf(-v)); }

DI void ldsm4(uint32_t* r, uint32_t addr) {
    asm volatile("ldmatrix.sync.aligned.m8n8.x4.shared.b16 {%0,%1,%2,%3}, [%4];"
                 : "=r"(r[0]), "=r"(r[1]), "=r"(r[2]), "=r"(r[3]) : "r"(addr));
}
DI void mma_f16(float* c, const uint32_t* a, const uint32_t* b) {
    asm volatile(
        "mma.sync.aligned.m16n8k16.row.col.f32.f16.f16.f32 "
        "{%0,%1,%2,%3}, {%4,%5,%6,%7}, {%8,%9}, {%0,%1,%2,%3};"
        : "+f"(c[0]), "+f"(c[1]), "+f"(c[2]), "+f"(c[3])
        : "r"(a[0]), "r"(a[1]), "r"(a[2]), "r"(a[3]), "r"(b[0]), "r"(b[1]));
}

// copy R rows x 128B (64 fp16) into smem rows padded to 144B
template <int R, int KDIM>
DI void cp_rows64(uint32_t sdst, const __half* g, int tid) {
#pragma unroll
    for (int it = 0; it < R * 8; it += 256) {
        int i = it + tid;
        int row = i >> 3, ch = i & 7;
        asm volatile("cp.async.cg.shared.global [%0], [%1], 16;"
                     :: "r"(sdst + row * 144 + ch * 16),
                        "l"((const char*)(g + (size_t)row * KDIM) + ch * 16));
    }
}
template <int KDIM>
DI void stage_cp(uint32_t sb, const __half* gA, const __half* gW, int k0, int tid) {
    cp_rows64<128, KDIM>(sb, gA + k0, tid);
    cp_rows64<128, KDIM>(sb + 128 * 144, gW + k0, tid);
}

DI uint4 pack8(float4 a, float4 b) {
    __half2 h0 = __float22half2_rn(make_float2(a.x, a.y));
    __half2 h1 = __float22half2_rn(make_float2(a.z, a.w));
    __half2 h2 = __float22half2_rn(make_float2(b.x, b.y));
    __half2 h3 = __float22half2_rn(make_float2(b.z, b.w));
    uint4 r;
    r.x = *(uint32_t*)&h0; r.y = *(uint32_t*)&h1;
    r.z = *(uint32_t*)&h2; r.w = *(uint32_t*)&h3;
    return r;
}

// ---- merged convert kernel: fp32 -> fp16, 8 elems/thread ----
#define NC_A1 (BB * K1 / 8)
#define NC_W1 ((int)((size_t)N1 * K1 / 8))
#define NC_W2 (EE * K2 / 8)
__global__ void k_conv(const float* __restrict__ x, const float* __restrict__ h,
                       const float* __restrict__ wxi, const float* __restrict__ whi_,
                       const float* __restrict__ wxg, const float* __restrict__ whg,
                       const float* __restrict__ wxf, const float* __restrict__ whf,
                       const float* __restrict__ wxo, const float* __restrict__ who_,
                       const float* __restrict__ why) {
    int idx = blockIdx.x * 256 + threadIdx.x;
    if (idx < NC_A1) {
        int i8 = idx * 8;
        int b = i8 / K1, k = i8 - b * K1;
        const float* src = (k < EE) ? &x[(size_t)b * EE + k] : &h[(size_t)b * HH + (k - EE)];
        *(uint4*)&g_A1[i8] = pack8(*(const float4*)src, *(const float4*)(src + 4));
    } else if (idx < NC_A1 + NC_W1) {
        size_t i8 = (size_t)(idx - NC_A1) * 8;
        int n = (int)(i8 / K1);                  // interleaved row: n' = 4*j + gate
        int k = (int)(i8 - (size_t)n * K1);
        int j = n >> 2, g = n & 3;
        const float* src;
        if (k < EE) {
            const float* a = (g == 0) ? wxi : (g == 1) ? wxg : (g == 2) ? wxf : wxo;
            src = &a[(size_t)j * EE + k];
        } else {
            const float* a = (g == 0) ? whi_ : (g == 1) ? whg : (g == 2) ? whf : who_;
            src = &a[(size_t)j * HH + (k - EE)];
        }
        *(uint4*)&g_W1[i8] = pack8(*(const float4*)src, *(const float4*)(src + 4));
    } else if (idx < NC_A1 + NC_W1 + NC_W2) {
        int i8 = (idx - NC_A1 - NC_W1) * 8;
        *(uint4*)&g_W2[i8] = pack8(*(const float4*)&why[i8], *(const float4*)&why[i8 + 4]);
    }
}

// ---- fp16 HMMA GEMM: CTA 128x128, warp 64x32, BK=64, 3-stage rotated ring ----
// MODE 0: gate-interleaved preact + fused gates epilogue -> out(c,h), g_A2
// MODE 1: split-K partial -> g_Part[z][b][n]  (k-chunk = S*64)
template <int S, int KDIM, int MODE>
__global__ void __launch_bounds__(256, 2)
k_gemm(const float* __restrict__ cin,
       const float* __restrict__ Bi, const float* __restrict__ Bg,
       const float* __restrict__ Bf, const float* __restrict__ Bo,
       float* __restrict__ outp) {
    constexpr int MI = 4, NI = 4;                 // warp tile 64x32
    constexpr int STAGE = 256 * 144;

    extern __shared__ char smem[];
    uint32_t sbase = smem_u32(smem);
    const int tid = threadIdx.x, lane = tid & 31, wid = tid >> 5;
    const int wm = (wid & 1) * 64, wn = (wid >> 1) * 32;   // 2 x 4 warp grid
    const int nt = blockIdx.x, mt = blockIdx.y;
    const int kOff = MODE ? blockIdx.z * (S * 64) : 0;

    const __half* gA = (MODE == 0 ? g_A1 : g_A2) + (size_t)mt * 128 * KDIM + kOff;
    const __half* gW = (MODE == 0 ? g_W1 : g_W2) + (size_t)nt * 128 * KDIM + kOff;

    float acc[MI][NI][4];
#pragma unroll
    for (int mi = 0; mi < MI; mi++)
#pragma unroll
        for (int ni = 0; ni < NI; ni++)
#pragma unroll
            for (int q = 0; q < 4; q++) acc[mi][ni][q] = 0.0f;

    stage_cp<KDIM>(sbase, gA, gW, 0, tid);
    asm volatile("cp.async.commit_group;" ::: "memory");
    stage_cp<KDIM>(sbase + STAGE, gA, gW, 64, tid);
    asm volatile("cp.async.commit_group;" ::: "memory");

    const uint32_t bRowOff = ((uint32_t)(((lane >> 4) << 3) + (lane & 7))) * 144
                           + ((lane >> 3) & 1) * 16;
    const uint32_t aRowOff = ((uint32_t)(lane & 15)) * 144 + (lane >> 4) * 16;

    // rotated ring pointers: cur = rb0, next = rb1, prefetch target = rb2
    uint32_t rb0 = sbase, rb1 = sbase + STAGE, rb2 = sbase + 2 * STAGE;

    for (int s = 0; s < S; ++s) {
        if (s + 1 < S)
            asm volatile("cp.async.wait_group 1;" ::: "memory");
        else
            asm volatile("cp.async.wait_group 0;" ::: "memory");
        __syncthreads();

        uint32_t sA = rb0 + (uint32_t)wm * 144 + aRowOff;
        uint32_t sW = rb0 + 128 * 144 + (uint32_t)wn * 144 + bRowOff;

        uint32_t Bb[2][NI][2], Ab[2][4];
#pragma unroll
        for (int nj = 0; nj < NI; nj += 2) {
            uint32_t r[4];
            ldsm4(r, sW + nj * 8 * 144);
            Bb[0][nj][0] = r[0]; Bb[0][nj][1] = r[1];
            Bb[0][nj + 1][0] = r[2]; Bb[0][nj + 1][1] = r[3];
        }
        ldsm4(Ab[0], sA);

        if (s + 2 < S) {
            stage_cp<KDIM>(rb2, gA, gW, (s + 2) * 64, tid);
            asm volatile("cp.async.commit_group;" ::: "memory");
        }

#pragma unroll
        for (int kk = 0; kk < 4; kk++) {
            if (kk < 3) {
#pragma unroll
                for (int nj = 0; nj < NI; nj += 2) {
                    uint32_t r[4];
                    ldsm4(r, sW + nj * 8 * 144 + (kk + 1) * 32);
                    Bb[(kk + 1) & 1][nj][0] = r[0]; Bb[(kk + 1) & 1][nj][1] = r[1];
                    Bb[(kk + 1) & 1][nj + 1][0] = r[2]; Bb[(kk + 1) & 1][nj + 1][1] = r[3];
                }
            }
#pragma unroll
            for (int mi = 0; mi < MI; mi++) {
                const int cur = (kk * MI + mi) & 1;
                if (mi + 1 < MI)
                    ldsm4(Ab[cur ^ 1], sA + (mi + 1) * 16 * 144 + kk * 32);
                else if (kk < 3)
                    ldsm4(Ab[cur ^ 1], sA + (kk + 1) * 32);
#pragma unroll
                for (int ni = 0; ni < NI; ni++)
                    mma_f16(acc[mi][ni], Ab[cur], Bb[kk & 1][ni]);
            }
        }
        uint32_t t = rb0; rb0 = rb1; rb1 = rb2; rb2 = t;   // rotate ring
    }

    if (MODE == 1) {
        float* dst = g_Part + (size_t)blockIdx.z * BB * EE;
#pragma unroll
        for (int mi = 0; mi < MI; mi++)
#pragma unroll
            for (int ni = 0; ni < NI; ni++) {
                int m = mt * 128 + wm + mi * 16 + (lane >> 2);
                int n = nt * 128 + wn + ni * 8 + (lane & 3) * 2;
                *(float2*)&dst[(size_t)m * EE + n] = make_float2(acc[mi][ni][0], acc[mi][ni][1]);
                *(float2*)&dst[(size_t)(m + 8) * EE + n] = make_float2(acc[mi][ni][2], acc[mi][ni][3]);
            }
    } else {
        // fused gates epilogue. sF (128x132 floats = 67.6 KB) overlaps stage buffers;
        // sync first so no warp still reads the final stage.
        float* sF = (float*)smem;
        __syncthreads();
#pragma unroll
        for (int mi = 0; mi < MI; mi++)
#pragma unroll
            for (int ni = 0; ni < NI; ni++) {
                int ml = wm + mi * 16 + (lane >> 2);
                int nl = wn + ni * 8 + (lane & 3) * 2;
                *(float2*)&sF[ml * 132 + nl] = make_float2(acc[mi][ni][0], acc[mi][ni][1]);
                *(float2*)&sF[(ml + 8) * 132 + nl] = make_float2(acc[mi][ni][2], acc[mi][ni][3]);
            }
        __syncthreads();
        const int j = nt * 32 + lane;
        const float bi = Bi[j], bg = Bg[j], bf = Bf[j], bo = Bo[j];
#pragma unroll 4
        for (int it = 0; it < 16; it++) {
            int ml = it * 8 + wid;
            float4 v = *(const float4*)&sF[ml * 132 + lane * 4];  // i,g,f,o preacts
            int b = mt * 128 + ml;
            float i = sigm(v.x + bi);
            float g = tanhf(v.y + bg);
            float f = sigm(v.z + bf);
            float o = sigm(v.w + bo);
            float cn = f * cin[(size_t)b * HH + j] + i * g;
            float hn = o * cn;
            outp[BB * EE + (size_t)b * HH + j] = cn;
            outp[BB * EE + BB * HH + (size_t)b * HH + j] = hn;
            g_A2[(size_t)b * HH + j] = __float2half(hn);
        }
    }
}

// ---- final y: reduce 4 split-K partials + bias + tanh ----
__global__ void k_y(const float* __restrict__ By, float* __restrict__ out) {
    int idx = blockIdx.x * 256 + threadIdx.x;
    if (idx >= BB * EE / 4) return;
    int base = idx * 4;
    int n = base & (EE - 1);
    float4 s0 = *(const float4*)&g_Part[base];
    float4 s1 = *(const float4*)&g_Part[BB * EE + base];
    float4 s2 = *(const float4*)&g_Part[2 * BB * EE + base];
    float4 s3 = *(const float4*)&g_Part[3 * BB * EE + base];
    float4 bv = *(const float4*)&By[n];
    float4 r;
    r.x = tanhf(s0.x + s1.x + s2.x + s3.x + bv.x);
    r.y = tanhf(s0.y + s1.y + s2.y + s3.y + bv.y);
    r.z = tanhf(s0.z + s1.z + s2.z + s3.z + bv.z);
    r.w = tanhf(s0.w + s1.w + s2.w + s3.w + bv.w);
    *(float4*)&out[base] = r;
}

extern "C" void kernel_launch(void* const* d_in, const int* in_sizes, int n_in,
                              void* d_out, int out_size) {
    const float* x   = (const float*)d_in[0];
    const float* c   = (const float*)d_in[1];
    const float* h   = (const float*)d_in[2];
    const float* wxi = (const float*)d_in[3];
    const float* whi = (const float*)d_in[4];
    const float* Bi  = (const float*)d_in[5];
    const float* wxg = (const float*)d_in[6];
    const float* whg = (const float*)d_in[7];
    const float* Bg  = (const float*)d_in[8];
    const float* wxf = (const float*)d_in[9];
    const float* whf = (const float*)d_in[10];
    const float* Bf  = (const float*)d_in[11];
    const float* wxo = (const float*)d_in[12];
    const float* who = (const float*)d_in[13];
    const float* Bo  = (const float*)d_in[14];
    const float* why = (const float*)d_in[15];
    const float* By  = (const float*)d_in[16];
    float* out = (float*)d_out;

    const int SMEM = 3 * 256 * 144;   // 110592
    cudaFuncSetAttribute(k_gemm<48, K1, 0>, cudaFuncAttributeMaxDynamicSharedMemorySize, SMEM);
    cudaFuncSetAttribute(k_gemm<8, K2, 1>, cudaFuncAttributeMaxDynamicSharedMemorySize, SMEM);

    const int NCHUNK = NC_A1 + NC_W1 + NC_W2;
    k_conv<<<(NCHUNK + 255) / 256, 256>>>(x, h, wxi, whi, wxg, whg, wxf, whf, wxo, who, why);
    k_gemm<48, K1, 0><<<dim3(N1 / 128, BB / 128), 256, SMEM>>>(c, Bi, Bg, Bf, Bo, out);
    k_gemm<8, K2, 1><<<dim3(EE / 128, BB / 128, 4), 256, SMEM>>>(
        nullptr, nullptr, nullptr, nullptr, nullptr, nullptr);
    k_y<<<(BB * EE / 4) / 256, 256>>>(By, out);
}

// round 13
// speedup vs baseline: 1.9090x; 1.0884x over previous
#include <cuda_runtime.h>
#include <cuda_fp16.h>
#include <stdint.h>
#include <math.h>

#define DI __device__ __forceinline__

#define BB 1024
#define HH 2048
#define EE 1024
#define K1 3072
#define N1 8192
#define K2 2048

// ---- device scratch ----
__device__ __align__(256) __half g_A1[BB * K1];
__device__ __align__(256) __half g_W1[(size_t)N1 * K1];   // gate-interleaved rows: n' = 4*j + gate
__device__ __align__(256) __half g_W2[EE * K2];
__device__ __align__(256) __half g_A2[BB * K2];
__device__ __align__(256) float g_Part[4 * BB * EE];      // split-K partials for GEMM2

// ---- helpers ----
DI uint32_t smem_u32(const void* p) {
    uint32_t a;
    asm("{ .reg .u64 t; cvta.to.shared.u64 t, %1; cvt.u32.u64 %0, t; }" : "=r"(a) : "l"(p));
    return a;
}
DI float sigm(float v) { return 1.0f / (1.0f + expf(-v)); }

DI void ldsm4(uint32_t* r, uint32_t addr) {
    asm volatile("ldmatrix.sync.aligned.m8n8.x4.shared.b16 {%0,%1,%2,%3}, [%4];"
                 : "=r"(r[0]), "=r"(r[1]), "=r"(r[2]), "=r"(r[3]) : "r"(addr));
}
DI void mma_f16(float* c, const uint32_t* a, const uint32_t* b) {
    asm volatile(
        "mma.sync.aligned.m16n8k16.row.col.f32.f16.f16.f32 "
        "{%0,%1,%2,%3}, {%4,%5,%6,%7}, {%8,%9}, {%0,%1,%2,%3};"
        : "+f"(c[0]), "+f"(c[1]), "+f"(c[2]), "+f"(c[3])
        : "r"(a[0]), "r"(a[1]), "r"(a[2]), "r"(a[3]), "r"(b[0]), "r"(b[1]));
}

// copy R rows x 128B (64 fp16) into smem rows padded to 144B
template <int R, int KDIM>
DI void cp_rows64(uint32_t sdst, const __half* g, int tid) {
#pragma unroll
    for (int it = 0; it < R * 8; it += 256) {
        int i = it + tid;
        int row = i >> 3, ch = i & 7;
        asm volatile("cp.async.cg.shared.global [%0], [%1], 16;"
                     :: "r"(sdst + row * 144 + ch * 16),
                        "l"((const char*)(g + (size_t)row * KDIM) + ch * 16));
    }
}
template <int KDIM>
DI void stage_cp(uint32_t sb, const __half* gA, const __half* gW, int k0, int tid) {
    cp_rows64<128, KDIM>(sb, gA + k0, tid);
    cp_rows64<128, KDIM>(sb + 128 * 144, gW + k0, tid);
}

DI uint4 pack8(float4 a, float4 b) {
    __half2 h0 = __float22half2_rn(make_float2(a.x, a.y));
    __half2 h1 = __float22half2_rn(make_float2(a.z, a.w));
    __half2 h2 = __float22half2_rn(make_float2(b.x, b.y));
    __half2 h3 = __float22half2_rn(make_float2(b.z, b.w));
    uint4 r;
    r.x = *(uint32_t*)&h0; r.y = *(uint32_t*)&h1;
    r.z = *(uint32_t*)&h2; r.w = *(uint32_t*)&h3;
    return r;
}

// ---- merged convert kernel: fp32 -> fp16, 16 elems/thread (2x uint4 stores) ----
#define NC_A1 (BB * K1 / 16)
#define NC_W1 ((int)((size_t)N1 * K1 / 16))
#define NC_W2 (EE * K2 / 16)
__global__ void __launch_bounds__(512)
k_conv(const float* __restrict__ x, const float* __restrict__ h,
       const float* __restrict__ wxi, const float* __restrict__ whi_,
       const float* __restrict__ wxg, const float* __restrict__ whg,
       const float* __restrict__ wxf, const float* __restrict__ whf,
       const float* __restrict__ wxo, const float* __restrict__ who_,
       const float* __restrict__ why) {
    int idx = blockIdx.x * 512 + threadIdx.x;
    const float* src;
    __half* dst;
    if (idx < NC_A1) {
        size_t i16 = (size_t)idx * 16;
        int b = (int)(i16 / K1), k = (int)(i16 - (size_t)b * K1);
        // 16-chunks never straddle the E boundary (EE multiple of 16)
        src = (k < EE) ? &x[(size_t)b * EE + k] : &h[(size_t)b * HH + (k - EE)];
        dst = &g_A1[i16];
    } else if (idx < NC_A1 + NC_W1) {
        size_t i16 = (size_t)(idx - NC_A1) * 16;
        int n = (int)(i16 / K1);                  // interleaved row: n' = 4*j + gate
        int k = (int)(i16 - (size_t)n * K1);
        int j = n >> 2, g = n & 3;
        if (k < EE) {
            const float* a = (g == 0) ? wxi : (g == 1) ? wxg : (g == 2) ? wxf : wxo;
            src = &a[(size_t)j * EE + k];
        } else {
            const float* a = (g == 0) ? whi_ : (g == 1) ? whg : (g == 2) ? whf : who_;
            src = &a[(size_t)j * HH + (k - EE)];
        }
        dst = &g_W1[i16];
    } else if (idx < NC_A1 + NC_W1 + NC_W2) {
        size_t i16 = (size_t)(idx - NC_A1 - NC_W1) * 16;
        src = &why[i16];
        dst = &g_W2[i16];
    } else {
        return;
    }
    float4 v0 = *(const float4*)src;
    float4 v1 = *(const float4*)(src + 4);
    float4 v2 = *(const float4*)(src + 8);
    float4 v3 = *(const float4*)(src + 12);
    *(uint4*)dst = pack8(v0, v1);
    *(uint4*)(dst + 8) = pack8(v2, v3);
}

// ---- fp16 HMMA GEMM: CTA 128x128, warp 64x32, BK=64, 3-stage ring (R7 mainloop) ----
// MODE 0: gate-interleaved preact + fused gates epilogue -> out(c,h), g_A2
// MODE 1: split-K partial -> g_Part[z][b][n]  (k-chunk = S*64)
template <int S, int KDIM, int MODE>
__global__ void __launch_bounds__(256, 2)
k_gemm(const float* __restrict__ cin,
       const float* __restrict__ Bi, const float* __restrict__ Bg,
       const float* __restrict__ Bf, const float* __restrict__ Bo,
       float* __restrict__ outp) {
    constexpr int MI = 4, NI = 4;                 // warp tile 64x32
    constexpr int STAGE = 256 * 144;

    extern __shared__ char smem[];
    uint32_t sbase = smem_u32(smem);
    const int tid = threadIdx.x, lane = tid & 31, wid = tid >> 5;
    const int wm = (wid & 1) * 64, wn = (wid >> 1) * 32;   // 2 x 4 warp grid
    const int nt = blockIdx.x, mt = blockIdx.y;
    const int kOff = MODE ? blockIdx.z * (S * 64) : 0;

    const __half* gA = (MODE == 0 ? g_A1 : g_A2) + (size_t)mt * 128 * KDIM + kOff;
    const __half* gW = (MODE == 0 ? g_W1 : g_W2) + (size_t)nt * 128 * KDIM + kOff;

    float acc[MI][NI][4];
#pragma unroll
    for (int mi = 0; mi < MI; mi++)
#pragma unroll
        for (int ni = 0; ni < NI; ni++)
#pragma unroll
            for (int q = 0; q < 4; q++) acc[mi][ni][q] = 0.0f;

    stage_cp<KDIM>(sbase, gA, gW, 0, tid);
    asm volatile("cp.async.commit_group;" ::: "memory");
    stage_cp<KDIM>(sbase + STAGE, gA, gW, 64, tid);
    asm volatile("cp.async.commit_group;" ::: "memory");

    const uint32_t bRowOff = ((uint32_t)(((lane >> 4) << 3) + (lane & 7))) * 144
                           + ((lane >> 3) & 1) * 16;
    const uint32_t aRowOff = ((uint32_t)(lane & 15)) * 144 + (lane >> 4) * 16;

    for (int s = 0; s < S; ++s) {
        if (s + 1 < S)
            asm volatile("cp.async.wait_group 1;" ::: "memory");
        else
            asm volatile("cp.async.wait_group 0;" ::: "memory");
        __syncthreads();

        uint32_t sb = sbase + (uint32_t)(s % 3) * STAGE;
        uint32_t sA = sb + (uint32_t)wm * 144 + aRowOff;
        uint32_t sW = sb + 128 * 144 + (uint32_t)wn * 144 + bRowOff;

        uint32_t Bb[2][NI][2], Ab[2][4];
#pragma unroll
        for (int nj = 0; nj < NI; nj += 2) {
            uint32_t r[4];
            ldsm4(r, sW + nj * 8 * 144);
            Bb[0][nj][0] = r[0]; Bb[0][nj][1] = r[1];
            Bb[0][nj + 1][0] = r[2]; Bb[0][nj + 1][1] = r[3];
        }
        ldsm4(Ab[0], sA);

        if (s + 2 < S) {
            stage_cp<KDIM>(sbase + ((s + 2) % 3) * STAGE, gA, gW, (s + 2) * 64, tid);
            asm volatile("cp.async.commit_group;" ::: "memory");
        }

#pragma unroll
        for (int kk = 0; kk < 4; kk++) {
            if (kk < 3) {
#pragma unroll
                for (int nj = 0; nj < NI; nj += 2) {
                    uint32_t r[4];
                    ldsm4(r, sW + nj * 8 * 144 + (kk + 1) * 32);
                    Bb[(kk + 1) & 1][nj][0] = r[0]; Bb[(kk + 1) & 1][nj][1] = r[1];
                    Bb[(kk + 1) & 1][nj + 1][0] = r[2]; Bb[(kk + 1) & 1][nj + 1][1] = r[3];
                }
            }
#pragma unroll
            for (int mi = 0; mi < MI; mi++) {
                const int cur = (kk * MI + mi) & 1;
                if (mi + 1 < MI)
                    ldsm4(Ab[cur ^ 1], sA + (mi + 1) * 16 * 144 + kk * 32);
                else if (kk < 3)
                    ldsm4(Ab[cur ^ 1], sA + (kk + 1) * 32);
#pragma unroll
                for (int ni = 0; ni < NI; ni++)
                    mma_f16(acc[mi][ni], Ab[cur], Bb[kk & 1][ni]);
            }
        }
    }

    if (MODE == 1) {
        float* dst = g_Part + (size_t)blockIdx.z * BB * EE;
#pragma unroll
        for (int mi = 0; mi < MI; mi++)
#pragma unroll
            for (int ni = 0; ni < NI; ni++) {
                int m = mt * 128 + wm + mi * 16 + (lane >> 2);
                int n = nt * 128 + wn + ni * 8 + (lane & 3) * 2;
                *(float2*)&dst[(size_t)m * EE + n] = make_float2(acc[mi][ni][0], acc[mi][ni][1]);
                *(float2*)&dst[(size_t)(m + 8) * EE + n] = make_float2(acc[mi][ni][2], acc[mi][ni][3]);
            }
    } else {
        // fused gates epilogue. Prefetch cin BEFORE the transpose barriers so the
        // global latency hides behind them.
        const int j = nt * 32 + lane;
        float cpre[16];
#pragma unroll
        for (int it = 0; it < 16; it++)
            cpre[it] = cin[(size_t)(mt * 128 + it * 8 + wid) * HH + j];
        const float bi = Bi[j], bg = Bg[j], bf = Bf[j], bo = Bo[j];

        float* sF = (float*)smem;
        __syncthreads();
#pragma unroll
        for (int mi = 0; mi < MI; mi++)
#pragma unroll
            for (int ni = 0; ni < NI; ni++) {
                int ml = wm + mi * 16 + (lane >> 2);
                int nl = wn + ni * 8 + (lane & 3) * 2;
                *(float2*)&sF[ml * 132 + nl] = make_float2(acc[mi][ni][0], acc[mi][ni][1]);
                *(float2*)&sF[(ml + 8) * 132 + nl] = make_float2(acc[mi][ni][2], acc[mi][ni][3]);
            }
        __syncthreads();
#pragma unroll 4
        for (int it = 0; it < 16; it++) {
            int ml = it * 8 + wid;
            float4 v = *(const float4*)&sF[ml * 132 + lane * 4];  // i,g,f,o preacts
            int b = mt * 128 + ml;
            float i = sigm(v.x + bi);
            float g = tanhf(v.y + bg);
            float f = sigm(v.z + bf);
            float o = sigm(v.w + bo);
            float cn = f * cpre[it] + i * g;
            float hn = o * cn;
            outp[BB * EE + (size_t)b * HH + j] = cn;
            outp[BB * EE + BB * HH + (size_t)b * HH + j] = hn;
            g_A2[(size_t)b * HH + j] = __float2half(hn);
        }
    }
}

// ---- final y: reduce 4 split-K partials + bias + tanh, 2 chunks/thread ----
__global__ void k_y(const float* __restrict__ By, float* __restrict__ out) {
    int t = blockIdx.x * 256 + threadIdx.x;
#pragma unroll
    for (int u = 0; u < 2; u++) {
        int idx = t + u * (BB * EE / 8);
        int base = idx * 4;
        int n = base & (EE - 1);
        float4 s0 = *(const float4*)&g_Part[base];
        float4 s1 = *(const float4*)&g_Part[BB * EE + base];
        float4 s2 = *(const float4*)&g_Part[2 * BB * EE + base];
        float4 s3 = *(const float4*)&g_Part[3 * BB * EE + base];
        float4 bv = *(const float4*)&By[n];
        float4 r;
        r.x = tanhf(s0.x + s1.x + s2.x + s3.x + bv.x);
        r.y = tanhf(s0.y + s1.y + s2.y + s3.y + bv.y);
        r.z = tanhf(s0.z + s1.z + s2.z + s3.z + bv.z);
        r.w = tanhf(s0.w + s1.w + s2.w + s3.w + bv.w);
        *(float4*)&out[base] = r;
    }
}

extern "C" void kernel_launch(void* const* d_in, const int* in_sizes, int n_in,
                              void* d_out, int out_size) {
    const float* x   = (const float*)d_in[0];
    const float* c   = (const float*)d_in[1];
    const float* h   = (const float*)d_in[2];
    const float* wxi = (const float*)d_in[3];
    const float* whi = (const float*)d_in[4];
    const float* Bi  = (const float*)d_in[5];
    const float* wxg = (const float*)d_in[6];
    const float* whg = (const float*)d_in[7];
    const float* Bg  = (const float*)d_in[8];
    const float* wxf = (const float*)d_in[9];
    const float* whf = (const float*)d_in[10];
    const float* Bf  = (const float*)d_in[11];
    const float* wxo = (const float*)d_in[12];
    const float* who = (const float*)d_in[13];
    const float* Bo  = (const float*)d_in[14];
    const float* why = (const float*)d_in[15];
    const float* By  = (const float*)d_in[16];
    float* out = (float*)d_out;

    const int SMEM = 3 * 256 * 144;   // 110592
    cudaFuncSetAttribute(k_gemm<48, K1, 0>, cudaFuncAttributeMaxDynamicSharedMemorySize, SMEM);
    cudaFuncSetAttribute(k_gemm<8, K2, 1>, cudaFuncAttributeMaxDynamicSharedMemorySize, SMEM);

    const int NCHUNK = NC_A1 + NC_W1 + NC_W2;
    k_conv<<<(NCHUNK + 511) / 512, 512>>>(x, h, wxi, whi, wxg, whg, wxf, whf, wxo, who, why);
    k_gemm<48, K1, 0><<<dim3(N1 / 128, BB / 128), 256, SMEM>>>(c, Bi, Bg, Bf, Bo, out);
    k_gemm<8, K2, 1><<<dim3(EE / 128, BB / 128, 4), 256, SMEM>>>(
        nullptr, nullptr, nullptr, nullptr, nullptr, nullptr);
    k_y<<<(BB * EE / 8) / 256, 256>>>(By, out);
}